// round 7
// baseline (speedup 1.0000x reference)
#include <cuda_runtime.h>

#define NN 2048
#define BB 4
#define THREADS 128
#define ROWS_PER_BLOCK 8                         // 2 row-groups x 4 rows
#define BLOCKS_PER_BATCH (NN / ROWS_PER_BLOCK)   // 256
#define CHUNK 512
#define NCHUNKS (NN / CHUNK)                     // 4

typedef unsigned long long u64;

__device__ __forceinline__ void fma2(u64& d, u64 a, u64 b) {
    asm("fma.rn.f32x2 %0, %1, %2, %0;" : "+l"(d) : "l"(a), "l"(b));
}
__device__ __forceinline__ u64 pack2(float lo, float hi) {
    u64 r;
    asm("mov.b64 %0, {%1, %2};" : "=l"(r) : "f"(lo), "f"(hi));
    return r;
}
__device__ __forceinline__ void unpack2(float& lo, float& hi, u64 v) {
    asm("mov.b64 {%0, %1}, %2;" : "=f"(lo), "=f"(hi) : "l"(v));
}
__device__ __forceinline__ u64 add2(u64 a, u64 b) {
    u64 r;
    asm("add.rn.f32x2 %0, %1, %2;" : "=l"(r) : "l"(a), "l"(b));
    return r;
}

__global__ __launch_bounds__(THREADS, 7)
void kuramoto_kernel(const float* __restrict__ W,
                     const float* __restrict__ alpha,
                     const float4* __restrict__ theta,
                     const float4* __restrict__ gamma,
                     float4* __restrict__ out) {
    __shared__ float4 s_sh[CHUNK];           // 8 KB (contiguous, conflict-free)
    __shared__ float4 c_sh[CHUNK];           // 8 KB
    __shared__ u64 red[4][4][4];             // [warp][r][P01,P23,Q01,Q23]

    const int b    = blockIdx.x / BLOCKS_PER_BATCH;
    const int row0 = (blockIdx.x % BLOCKS_PER_BATCH) * ROWS_PER_BLOCK;
    const int base = b * NN;

    const int warp   = threadIdx.x >> 5;
    const int lane   = threadIdx.x & 31;
    const int rowgrp = warp >> 1;            // warps {0,1}->rows 0-3, {2,3}->rows 4-7
    const int jhalf  = warp & 1;             // j half of each chunk
    const int i0     = row0 + rowgrp * 4;    // first of this warp's 4 rows

    // One base pointer per array; rows indexed by constant r*NN offsets.
    const float* __restrict__ Wr = W     + (size_t)(base + i0) * NN;
    const float* __restrict__ Ar = alpha + (size_t)(base + i0) * NN;

    u64 P01[4], P23[4], Q01[4], Q23[4];
    #pragma unroll
    for (int r = 0; r < 4; ++r) { P01[r] = 0; P23[r] = 0; Q01[r] = 0; Q23[r] = 0; }

    for (int ch = 0; ch < NCHUNKS; ++ch) {
        __syncthreads();
        // Build this chunk's sin/cos table in-kernel from theta (L2-resident)
        #pragma unroll
        for (int t = 0; t < CHUNK; t += THREADS) {
            const int idx = t + threadIdx.x;
            const float4 th = theta[base + ch * CHUNK + idx];
            float4 s, c;
            __sincosf(th.x, &s.x, &c.x);
            __sincosf(th.y, &s.y, &c.y);
            __sincosf(th.z, &s.z, &c.z);
            __sincosf(th.w, &s.w, &c.w);
            s_sh[idx] = s;
            c_sh[idx] = c;
        }
        __syncthreads();

        const int chbase = ch * CHUNK;

        #pragma unroll 2
        for (int it = 0; it < CHUNK / 2 / 32; ++it) {    // 8 iters of 32 j
            const int jloc = jhalf * (CHUNK / 2) + it * 32 + lane;  // chunk-local j
            const int goff = chbase + jloc;

            // Batch 8 coalesced LDG.32 (4 rows x W,alpha)
            float w[4], a[4];
            #pragma unroll
            for (int r = 0; r < 4; ++r) {
                w[r] = __ldg(Wr + (size_t)r * NN + goff);
                a[r] = __ldg(Ar + (size_t)r * NN + goff);
            }

            // Table read ONCE per 32 j's, reused for all 4 rows
            const ulonglong2 sp = *reinterpret_cast<const ulonglong2*>(&s_sh[jloc]);
            const ulonglong2 cp = *reinterpret_cast<const ulonglong2*>(&c_sh[jloc]);

            #pragma unroll
            for (int r = 0; r < 4; ++r) {
                float sa, ca;
                __sincosf(a[r], &sa, &ca);
                const float Av = w[r] * ca;          // W * cos(alpha)
                const float Bv = w[r] * sa;          // W * sin(alpha)
                const u64 Av2  = pack2(Av, Av);
                const u64 Bv2  = pack2(Bv, Bv);
                const u64 nBv2 = pack2(-Bv, -Bv);
                // P += Av*c + Bv*s ;  Q += Av*s - Bv*c   (packed d-pairs)
                fma2(P01[r], Av2, cp.x);  fma2(P01[r], Bv2, sp.x);
                fma2(P23[r], Av2, cp.y);  fma2(P23[r], Bv2, sp.y);
                fma2(Q01[r], Av2, sp.x);  fma2(Q01[r], nBv2, cp.x);
                fma2(Q23[r], Av2, sp.y);  fma2(Q23[r], nBv2, cp.y);
            }
        }
    }

    // Butterfly: reduce all 4 rows' packed sums across the 32 lanes
    #pragma unroll
    for (int off = 16; off > 0; off >>= 1) {
        #pragma unroll
        for (int r = 0; r < 4; ++r) {
            P01[r] = add2(P01[r], __shfl_xor_sync(0xffffffffu, P01[r], off));
            P23[r] = add2(P23[r], __shfl_xor_sync(0xffffffffu, P23[r], off));
            Q01[r] = add2(Q01[r], __shfl_xor_sync(0xffffffffu, Q01[r], off));
            Q23[r] = add2(Q23[r], __shfl_xor_sync(0xffffffffu, Q23[r], off));
        }
    }

    if (lane == 0) {
        #pragma unroll
        for (int r = 0; r < 4; ++r) {
            red[warp][r][0] = P01[r];  red[warp][r][1] = P23[r];
            red[warp][r][2] = Q01[r];  red[warp][r][3] = Q23[r];
        }
    }
    __syncthreads();

    // 8 threads: one output row each; combine the two j-half warps
    if (threadIdx.x < ROWS_PER_BLOCK) {
        const int g = threadIdx.x >> 2;      // row-group
        const int r = threadIdx.x & 3;       // row within group
        const int i = row0 + g * 4 + r;

        const u64 p01 = add2(red[2 * g][r][0], red[2 * g + 1][r][0]);
        const u64 p23 = add2(red[2 * g][r][1], red[2 * g + 1][r][1]);
        const u64 q01 = add2(red[2 * g][r][2], red[2 * g + 1][r][2]);
        const u64 q23 = add2(red[2 * g][r][3], red[2 * g + 1][r][3]);

        float P0, P1, P2, P3, Q0, Q1, Q2, Q3;
        unpack2(P0, P1, p01); unpack2(P2, P3, p23);
        unpack2(Q0, Q1, q01); unpack2(Q2, Q3, q23);

        const float invn = 1.0f / (float)NN;     // COUPLING / N
        const float4 g4 = gamma[base + i];
        const float4 th = theta[base + i];
        float4 si, ci;
        __sincosf(th.x, &si.x, &ci.x);
        __sincosf(th.y, &si.y, &ci.y);
        __sincosf(th.z, &si.z, &ci.z);
        __sincosf(th.w, &si.w, &ci.w);

        // theta_next = gamma + (1/N)(c_i*Q - s_i*P)   (theta cancels, DT=ATTR=1)
        float n0 = g4.x + invn * (ci.x * Q0 - si.x * P0);
        float n1 = g4.y + invn * (ci.y * Q1 - si.y * P1);
        float n2 = g4.z + invn * (ci.z * Q2 - si.z * P2);
        float n3 = g4.w + invn * (ci.w * Q3 - si.w * P3);

        float nrm = sqrtf(n0 * n0 + n1 * n1 + n2 * n2 + n3 * n3);
        float inv = 1.0f / fmaxf(nrm, 1e-6f);
        out[base + i] = make_float4(n0 * inv, n1 * inv, n2 * inv, n3 * inv);
    }
}

extern "C" void kernel_launch(void* const* d_in, const int* in_sizes, int n_in,
                              void* d_out, int out_size) {
    const float* theta = (const float*)d_in[0];   // [B, N, 4]
    const float* gamma = (const float*)d_in[1];   // [B, N, 4]
    const float* W     = (const float*)d_in[2];   // [B, N, N]
    const float* alpha = (const float*)d_in[3];   // [B, N, N]
    float* out = (float*)d_out;                   // [B, N, 4]

    // Single fused kernel: 1024 blocks x 128 threads; 4 rows/warp share each
    // table read (LDS wf halved vs R6); single wave at 7 CTAs/SM.
    kuramoto_kernel<<<BB * BLOCKS_PER_BATCH, THREADS>>>(
        W, alpha, (const float4*)theta, (const float4*)gamma, (float4*)out);
}

// round 8
// speedup vs baseline: 1.2062x; 1.2062x over previous
#include <cuda_runtime.h>
#include <cstdint>

#define NN 2048
#define BB 4
#define THREADS 128
#define ROWS_PER_BLOCK 8                         // 2 row-groups x 4 rows
#define BLOCKS_PER_BATCH (NN / ROWS_PER_BLOCK)   // 256
#define CHUNK 512
#define NCHUNKS (NN / CHUNK)                     // 4
#define NWIN 32                                  // total windows per warp (4 ch x 8 it)
#define NSTAGES 3
#define STAGE_BYTES 1024                         // 4 rows x 32 j x 4B x 2 arrays

typedef unsigned long long u64;

__device__ __forceinline__ void fma2(u64& d, u64 a, u64 b) {
    asm("fma.rn.f32x2 %0, %1, %2, %0;" : "+l"(d) : "l"(a), "l"(b));
}
__device__ __forceinline__ u64 pack2(float lo, float hi) {
    u64 r;
    asm("mov.b64 %0, {%1, %2};" : "=l"(r) : "f"(lo), "f"(hi));
    return r;
}
__device__ __forceinline__ void unpack2(float& lo, float& hi, u64 v) {
    asm("mov.b64 {%0, %1}, %2;" : "=f"(lo), "=f"(hi) : "l"(v));
}
__device__ __forceinline__ u64 add2(u64 a, u64 b) {
    u64 r;
    asm("add.rn.f32x2 %0, %1, %2;" : "=l"(r) : "l"(a), "l"(b));
    return r;
}
__device__ __forceinline__ void cp16(uint32_t dst_smem, const void* src) {
    asm volatile("cp.async.cg.shared.global [%0], [%1], 16;"
                 :: "r"(dst_smem), "l"(src));
}
#define CP_COMMIT() asm volatile("cp.async.commit_group;")
#define CP_WAIT2()  asm volatile("cp.async.wait_group 2;")

__global__ __launch_bounds__(THREADS, 7)
void kuramoto_kernel(const float* __restrict__ W,
                     const float* __restrict__ alpha,
                     const float4* __restrict__ theta,
                     const float4* __restrict__ gamma,
                     float4* __restrict__ out) {
    __shared__ float4 s_sh[CHUNK];                            // 8 KB
    __shared__ float4 c_sh[CHUNK];                            // 8 KB
    __shared__ __align__(16) char stage[4][NSTAGES][STAGE_BYTES];  // 12 KB
    __shared__ u64 red[4][4][4];                              // [warp][r][P01,P23,Q01,Q23]

    const int b    = blockIdx.x / BLOCKS_PER_BATCH;
    const int row0 = (blockIdx.x % BLOCKS_PER_BATCH) * ROWS_PER_BLOCK;
    const int base = b * NN;

    const int warp   = threadIdx.x >> 5;
    const int lane   = threadIdx.x & 31;
    const int rowgrp = warp >> 1;             // rows 0-3 / 4-7
    const int jpart  = warp & 1;              // chunk j-half
    const int i0     = row0 + rowgrp * 4;     // first of this warp's 4 rows

    const float* __restrict__ Wr = W     + (size_t)(base + i0) * NN;
    const float* __restrict__ Ar = alpha + (size_t)(base + i0) * NN;

    // This lane's LDGSTS source offsets: row = lane>>3, jseg = 4*(lane&7)
    const size_t src_row_off = (size_t)(lane >> 3) * NN + 4 * (lane & 7);
    const uint32_t my_stage =
        (uint32_t)__cvta_generic_to_shared(&stage[warp][0][0]) + lane * 16;
    const char* stage_rd = &stage[warp][0][0];

    u64 P01[4], P23[4], Q01[4], Q23[4];
    #pragma unroll
    for (int r = 0; r < 4; ++r) { P01[r] = 0; P23[r] = 0; Q01[r] = 0; Q23[r] = 0; }

    // Prologue: prefetch windows 0..2
    #pragma unroll
    for (int w = 0; w < NSTAGES; ++w) {
        const int woff = (w >> 3) * CHUNK + jpart * 256 + (w & 7) * 32;
        const uint32_t dst = my_stage + w * STAGE_BYTES;   // slot = w (w<3)
        cp16(dst,       Wr + src_row_off + woff);
        cp16(dst + 512, Ar + src_row_off + woff);
        CP_COMMIT();
    }

    for (int w = 0; w < NWIN; ++w) {
        // Rebuild the sin/cos table at chunk boundaries
        if ((w & 7) == 0) {
            __syncthreads();   // everyone done reading old table
            const int ch = w >> 3;
            #pragma unroll
            for (int t = 0; t < CHUNK; t += THREADS) {
                const int idx = t + threadIdx.x;
                const float4 th = theta[base + ch * CHUNK + idx];
                float4 s, c;
                __sincosf(th.x, &s.x, &c.x);
                __sincosf(th.y, &s.y, &c.y);
                __sincosf(th.z, &s.z, &c.z);
                __sincosf(th.w, &s.w, &c.w);
                s_sh[idx] = s;
                c_sh[idx] = c;
            }
        }

        CP_WAIT2();            // window w's group complete (for this thread)
        __syncthreads();       // cross-thread visibility: cp.async data + table

        // ---- compute window w ----
        const int slot = w % NSTAGES;
        const int jloc = jpart * 256 + (w & 7) * 32 + lane;   // chunk-local j

        const ulonglong2 sp = *reinterpret_cast<const ulonglong2*>(&s_sh[jloc]);
        const ulonglong2 cp = *reinterpret_cast<const ulonglong2*>(&c_sh[jloc]);
        const char* st = stage_rd + slot * STAGE_BYTES;

        #pragma unroll
        for (int r = 0; r < 4; ++r) {
            const float wv = *reinterpret_cast<const float*>(st + r * 128 + lane * 4);
            const float av = *reinterpret_cast<const float*>(st + 512 + r * 128 + lane * 4);
            float sa, ca;
            __sincosf(av, &sa, &ca);
            const float Av = wv * ca;            // W * cos(alpha)
            const float Bv = wv * sa;            // W * sin(alpha)
            const u64 Av2  = pack2(Av, Av);
            const u64 Bv2  = pack2(Bv, Bv);
            const u64 nBv2 = pack2(-Bv, -Bv);
            // P += Av*c + Bv*s ;  Q += Av*s - Bv*c   (packed d-pairs)
            fma2(P01[r], Av2, cp.x);  fma2(P01[r], Bv2, sp.x);
            fma2(P23[r], Av2, cp.y);  fma2(P23[r], Bv2, sp.y);
            fma2(Q01[r], Av2, sp.x);  fma2(Q01[r], nBv2, cp.x);
            fma2(Q23[r], Av2, sp.y);  fma2(Q23[r], nBv2, cp.y);
        }

        // Prefetch window w+3 into the slot just freed (slot == w % 3)
        if (w + NSTAGES < NWIN) {
            const int wn   = w + NSTAGES;
            const int woff = (wn >> 3) * CHUNK + jpart * 256 + (wn & 7) * 32;
            const uint32_t dst = my_stage + slot * STAGE_BYTES;
            cp16(dst,       Wr + src_row_off + woff);
            cp16(dst + 512, Ar + src_row_off + woff);
        }
        CP_COMMIT();           // always commit (possibly empty) to keep group count
    }

    // Butterfly: reduce all 4 rows' packed sums across the 32 lanes
    #pragma unroll
    for (int off = 16; off > 0; off >>= 1) {
        #pragma unroll
        for (int r = 0; r < 4; ++r) {
            P01[r] = add2(P01[r], __shfl_xor_sync(0xffffffffu, P01[r], off));
            P23[r] = add2(P23[r], __shfl_xor_sync(0xffffffffu, P23[r], off));
            Q01[r] = add2(Q01[r], __shfl_xor_sync(0xffffffffu, Q01[r], off));
            Q23[r] = add2(Q23[r], __shfl_xor_sync(0xffffffffu, Q23[r], off));
        }
    }

    if (lane == 0) {
        #pragma unroll
        for (int r = 0; r < 4; ++r) {
            red[warp][r][0] = P01[r];  red[warp][r][1] = P23[r];
            red[warp][r][2] = Q01[r];  red[warp][r][3] = Q23[r];
        }
    }
    __syncthreads();

    // 8 threads: one output row each; combine the two j-half warps
    if (threadIdx.x < ROWS_PER_BLOCK) {
        const int g = threadIdx.x >> 2;      // row-group
        const int r = threadIdx.x & 3;       // row within group
        const int i = row0 + g * 4 + r;

        const u64 p01 = add2(red[2 * g][r][0], red[2 * g + 1][r][0]);
        const u64 p23 = add2(red[2 * g][r][1], red[2 * g + 1][r][1]);
        const u64 q01 = add2(red[2 * g][r][2], red[2 * g + 1][r][2]);
        const u64 q23 = add2(red[2 * g][r][3], red[2 * g + 1][r][3]);

        float P0, P1, P2, P3, Q0, Q1, Q2, Q3;
        unpack2(P0, P1, p01); unpack2(P2, P3, p23);
        unpack2(Q0, Q1, q01); unpack2(Q2, Q3, q23);

        const float invn = 1.0f / (float)NN;     // COUPLING / N
        const float4 g4 = gamma[base + i];
        const float4 th = theta[base + i];
        float4 si, ci;
        __sincosf(th.x, &si.x, &ci.x);
        __sincosf(th.y, &si.y, &ci.y);
        __sincosf(th.z, &si.z, &ci.z);
        __sincosf(th.w, &si.w, &ci.w);

        // theta_next = gamma + (1/N)(c_i*Q - s_i*P)   (theta cancels, DT=ATTR=1)
        float n0 = g4.x + invn * (ci.x * Q0 - si.x * P0);
        float n1 = g4.y + invn * (ci.y * Q1 - si.y * P1);
        float n2 = g4.z + invn * (ci.z * Q2 - si.z * P2);
        float n3 = g4.w + invn * (ci.w * Q3 - si.w * P3);

        float nrm = sqrtf(n0 * n0 + n1 * n1 + n2 * n2 + n3 * n3);
        float inv = 1.0f / fmaxf(nrm, 1e-6f);
        out[base + i] = make_float4(n0 * inv, n1 * inv, n2 * inv, n3 * inv);
    }
}

extern "C" void kernel_launch(void* const* d_in, const int* in_sizes, int n_in,
                              void* d_out, int out_size) {
    const float* theta = (const float*)d_in[0];   // [B, N, 4]
    const float* gamma = (const float*)d_in[1];   // [B, N, 4]
    const float* W     = (const float*)d_in[2];   // [B, N, N]
    const float* alpha = (const float*)d_in[3];   // [B, N, N]
    float* out = (float*)d_out;                   // [B, N, 4]

    // Single fused kernel: cp.async 3-stage pipeline for W/alpha (register-free
    // latency hiding), table shared across 4 rows/lane, single wave @7 CTAs/SM.
    kuramoto_kernel<<<BB * BLOCKS_PER_BATCH, THREADS>>>(
        W, alpha, (const float4*)theta, (const float4*)gamma, (float4*)out);
}